// round 12
// baseline (speedup 1.0000x reference)
#include <cuda_runtime.h>
#include <math.h>

#define NN 50000
#define NE 800000
#define GD 128
#define LG 16

// ---- scratch (device globals: no allocations allowed) ----
__device__ float g_ns [NN * LG];        // silu(node_s @ Wns + bns)
__device__ float g_nv [NN * 3 * LG];    // node_v @ Wnv
__device__ float g_nvn[NN * LG];        // ||nv||_spatial
__device__ float g_nes[NN * LG];        // segment_sum(es_upd)
__device__ float g_nev[NN * 3 * LG];    // segment_sum(ev_upd)

typedef unsigned long long u64;
typedef ulonglong2 u64x2;

__device__ __forceinline__ float siluf(float x)  { return x / (1.0f + __expf(-x)); }
__device__ __forceinline__ float sigmf(float x)  { return 1.0f / (1.0f + __expf(-x)); }

__device__ __forceinline__ u64 dup2(float v) {
    u64 r; asm("mov.b64 %0, {%1, %1};" : "=l"(r) : "f"(v)); return r;
}
__device__ __forceinline__ u64 pk2(float lo, float hi) {
    u64 r; asm("mov.b64 %0, {%1, %2};" : "=l"(r) : "f"(lo), "f"(hi)); return r;
}
__device__ __forceinline__ void up2(u64 v, float& lo, float& hi) {
    asm("mov.b64 {%0, %1}, %2;" : "=f"(lo), "=f"(hi) : "l"(v));
}
__device__ __forceinline__ void fma2(u64& d, u64 a, u64 b) {
    asm("fma.rn.f32x2 %0, %1, %2, %0;" : "+l"(d) : "l"(a), "l"(b));
}
__device__ __forceinline__ u64 mul2(u64 a, u64 b) {
    u64 r; asm("mul.rn.f32x2 %0, %1, %2;" : "=l"(r) : "l"(a), "l"(b)); return r;
}
__device__ __forceinline__ u64 add2(u64 a, u64 b) {
    u64 r; asm("add.rn.f32x2 %0, %1, %2;" : "=l"(r) : "l"(a), "l"(b)); return r;
}
__device__ __forceinline__ void red_v4(float* p, float a, float b, float c, float d) {
    asm volatile("red.global.add.v4.f32 [%0], {%1, %2, %3, %4};"
                 :: "l"(p), "f"(a), "f"(b), "f"(c), "f"(d) : "memory");
}

// ============================================================================
// Kernel A: node input projections — quad per node, f32x2, grid-stride
// ============================================================================
__global__ void __launch_bounds__(256, 4) k_node_pre(
    const float* __restrict__ node_s, const float* __restrict__ node_v,
    const float* __restrict__ Wns,    const float* __restrict__ bns,
    const float* __restrict__ Wnv)
{
    __shared__ __align__(16) float sWns[GD * LG];
    __shared__ __align__(16) float sWnv[GD * LG];
    for (int i = threadIdx.x; i < GD * LG; i += blockDim.x) {
        sWns[i] = Wns[i];
        sWnv[i] = Wnv[i];
    }
    // zero the edge-aggregation accumulators
    {
        int idx = blockIdx.x * blockDim.x + threadIdx.x;
        int tot = gridDim.x * blockDim.x;
        float4 z = make_float4(0.f, 0.f, 0.f, 0.f);
        float4* pes = (float4*)g_nes;
        float4* pev = (float4*)g_nev;
        for (int i = idx; i < NN * LG / 4; i += tot)     pes[i] = z;
        for (int i = idx; i < NN * 3 * LG / 4; i += tot) pev[i] = z;
    }
    __syncthreads();

    const int t  = threadIdx.x;
    const int lq = (t & 3) * 4;
    const unsigned qb = (unsigned)((t & 31) & 28);

    for (int nb = blockIdx.x; nb < (NN + 63) / 64; nb += gridDim.x) {
        int n = nb * 64 + (t >> 2);
        const bool valid = (n < NN);
        if (!valid) n = NN - 1;

        const float* srow = node_s + (size_t)n * GD;
        const float* vrow = node_v + (size_t)n * 3 * GD;

        u64 ans0 = 0, ans1 = 0;
        u64 a00 = 0, a01 = 0, a10 = 0, a11 = 0, a20 = 0, a21 = 0;

        for (int tile = 0; tile < 8; tile++) {        // 16 g per tile
            const int off = tile * 16 + lq;
            float4 sA = __ldg((const float4*)(srow + off));
            float4 vA0 = __ldg((const float4*)(vrow + off));
            float4 vA1 = __ldg((const float4*)(vrow + GD + off));
            float4 vA2 = __ldg((const float4*)(vrow + 2 * GD + off));
            float sr[4]  = { sA.x, sA.y, sA.z, sA.w };
            float v0r[4] = { vA0.x, vA0.y, vA0.z, vA0.w };
            float v1r[4] = { vA1.x, vA1.y, vA1.z, vA1.w };
            float v2r[4] = { vA2.x, vA2.y, vA2.z, vA2.w };
#pragma unroll
            for (int kq = 0; kq < 4; kq++) {
#pragma unroll
                for (int c = 0; c < 4; c++) {
                    const int gl = tile * 16 + kq * 4 + c;
                    u64 a  = dup2(__shfl_sync(0xffffffffu, sr[c],  qb + kq));
                    u64 b0 = dup2(__shfl_sync(0xffffffffu, v0r[c], qb + kq));
                    u64 b1 = dup2(__shfl_sync(0xffffffffu, v1r[c], qb + kq));
                    u64 b2 = dup2(__shfl_sync(0xffffffffu, v2r[c], qb + kq));
                    u64x2 w = *(const u64x2*)&sWns[gl * 16 + lq];
                    u64x2 u = *(const u64x2*)&sWnv[gl * 16 + lq];
                    fma2(ans0, a, w.x);  fma2(ans1, a, w.y);
                    fma2(a00, b0, u.x);  fma2(a01, b0, u.y);
                    fma2(a10, b1, u.x);  fma2(a11, b1, u.y);
                    fma2(a20, b2, u.x);  fma2(a21, b2, u.y);
                }
            }
        }

        if (valid) {
            float s0, s1, s2, s3;
            up2(ans0, s0, s1); up2(ans1, s2, s3);
            float4 bb = __ldg((const float4*)(bns + lq));
            float4 o;
            o.x = siluf(s0 + bb.x); o.y = siluf(s1 + bb.y);
            o.z = siluf(s2 + bb.z); o.w = siluf(s3 + bb.w);
            *(float4*)(g_ns + (size_t)n * LG + lq) = o;

            float4 w0, w1, w2;
            up2(a00, w0.x, w0.y); up2(a01, w0.z, w0.w);
            up2(a10, w1.x, w1.y); up2(a11, w1.z, w1.w);
            up2(a20, w2.x, w2.y); up2(a21, w2.z, w2.w);
            *(float4*)(g_nv + (size_t)n * 48 + lq)      = w0;
            *(float4*)(g_nv + (size_t)n * 48 + 16 + lq) = w1;
            *(float4*)(g_nv + (size_t)n * 48 + 32 + lq) = w2;
            float4 nn;
            nn.x = sqrtf(w0.x * w0.x + w1.x * w1.x + w2.x * w2.x + 1e-12f);
            nn.y = sqrtf(w0.y * w0.y + w1.y * w1.y + w2.y * w2.y + 1e-12f);
            nn.z = sqrtf(w0.z * w0.z + w1.z * w1.z + w2.z * w2.z + 1e-12f);
            nn.w = sqrtf(w0.w * w0.w + w1.w * w1.w + w2.w * w2.w + 1e-12f);
            *(float4*)(g_nvn + (size_t)n * LG + lq) = nn;
        }
    }
}

// ============================================================================
// Kernel B: edge update — quad per edge, f32x2, grid-stride, vector atomics
// ============================================================================
__global__ void __launch_bounds__(256, 4) k_edge(
    const float* __restrict__ edge_s, const float* __restrict__ edge_v,
    const float* __restrict__ dist,   const float* __restrict__ vctr,
    const int*   __restrict__ src,    const int*   __restrict__ dst,
    const float* __restrict__ Wen,    const float* __restrict__ ben,
    const float* __restrict__ Wtp,    const float* __restrict__ btp,
    const float* __restrict__ Wg1,    const float* __restrict__ bg1,
    const float* __restrict__ Wg2,    const float* __restrict__ bg2,
    const float* __restrict__ Wtv,    const float* __restrict__ btv,
    float* __restrict__ es_out,       float* __restrict__ ev_out)
{
    __shared__ __align__(16) float sWen[32 * 16], sWtp[16 * 16], sWg1[16 * 16], sWg2[16 * 16];
    __shared__ __align__(16) float sWtv[16 * 48];
    __shared__ __align__(16) float sben[16], sbtp[16], sbg1[16], sbg2[16], sbtv[48];
    const int t = threadIdx.x;
    for (int i = t; i < 512; i += 256) sWen[i] = Wen[i];
    if (t < 256) { sWtp[t] = Wtp[t]; sWg1[t] = Wg1[t]; sWg2[t] = Wg2[t]; }
    for (int i = t; i < 768; i += 256) sWtv[i] = Wtv[i];
    if (t < 16) { sben[t] = ben[t]; sbtp[t] = btp[t]; sbg1[t] = bg1[t]; sbg2[t] = bg2[t]; }
    if (t < 48) sbtv[t] = btv[t];
    __syncthreads();

    const int lq = (t & 3) * 4;
    const unsigned qb = (unsigned)((t & 31) & 28);
    const int eoff = t >> 2;

    for (int eb = blockIdx.x; eb < NE / 64; eb += gridDim.x) {
        const int e = eb * 64 + eoff;       // NE = 12500*64, exact
        const int s = src[e], d = dst[e];

        float nss[4], nsd[4], es[4];
        {
            float4 a = *(const float4*)(g_ns + (size_t)s * LG + lq);
            nss[0] = a.x; nss[1] = a.y; nss[2] = a.z; nss[3] = a.w;
            float4 b = *(const float4*)(g_ns + (size_t)d * LG + lq);
            nsd[0] = b.x; nsd[1] = b.y; nsd[2] = b.z; nsd[3] = b.w;
            float4 c = __ldg((const float4*)(edge_s + (size_t)e * LG + lq));
            es[0] = c.x; es[1] = c.y; es[2] = c.z; es[3] = c.w;
        }

        // en = [ns[src] | ns[dst]] @ Wen + ben
        u64 en0, en1;
        { u64x2 bb = *(const u64x2*)&sben[lq]; en0 = bb.x; en1 = bb.y; }
#pragma unroll
        for (int kq = 0; kq < 4; kq++) {
#pragma unroll
            for (int c = 0; c < 4; c++) {
                const int k = kq * 4 + c;
                u64 a2 = dup2(__shfl_sync(0xffffffffu, nss[c], qb + kq));
                u64 b2 = dup2(__shfl_sync(0xffffffffu, nsd[c], qb + kq));
                u64x2 w1 = *(const u64x2*)&sWen[k * 16 + lq];
                u64x2 w2 = *(const u64x2*)&sWen[(16 + k) * 16 + lq];
                fma2(en0, a2, w1.x); fma2(en1, a2, w1.y);
                fma2(en0, b2, w2.x); fma2(en1, b2, w2.y);
            }
        }
        // tp = edge_s @ Wtp + btp
        u64 tp0, tp1;
        { u64x2 bb = *(const u64x2*)&sbtp[lq]; tp0 = bb.x; tp1 = bb.y; }
#pragma unroll
        for (int kq = 0; kq < 4; kq++) {
#pragma unroll
            for (int c = 0; c < 4; c++) {
                const int k = kq * 4 + c;
                u64 a2 = dup2(__shfl_sync(0xffffffffu, es[c], qb + kq));
                u64x2 w = *(const u64x2*)&sWtp[k * 16 + lq];
                fma2(tp0, a2, w.x); fma2(tp1, a2, w.y);
            }
        }
        float tm[4];
        { u64 m0 = mul2(en0, tp0), m1 = mul2(en1, tp1);
          up2(m0, tm[0], tm[1]); up2(m1, tm[2], tm[3]); }

        // h = silu(tm @ Wg1 + bg1)
        u64 h0, h1;
        { u64x2 bb = *(const u64x2*)&sbg1[lq]; h0 = bb.x; h1 = bb.y; }
#pragma unroll
        for (int kq = 0; kq < 4; kq++) {
#pragma unroll
            for (int c = 0; c < 4; c++) {
                const int k = kq * 4 + c;
                u64 a2 = dup2(__shfl_sync(0xffffffffu, tm[c], qb + kq));
                u64x2 w = *(const u64x2*)&sWg1[k * 16 + lq];
                fma2(h0, a2, w.x); fma2(h1, a2, w.y);
            }
        }
        float hh[4];
        { float x0, x1, x2, x3; up2(h0, x0, x1); up2(h1, x2, x3);
          hh[0] = siluf(x0); hh[1] = siluf(x1); hh[2] = siluf(x2); hh[3] = siluf(x3); }

        // gate = sigmoid(h @ Wg2 + bg2), esu = gate * co
        u64 gg0, gg1;
        { u64x2 bb = *(const u64x2*)&sbg2[lq]; gg0 = bb.x; gg1 = bb.y; }
#pragma unroll
        for (int kq = 0; kq < 4; kq++) {
#pragma unroll
            for (int c = 0; c < 4; c++) {
                const int k = kq * 4 + c;
                u64 a2 = dup2(__shfl_sync(0xffffffffu, hh[c], qb + kq));
                u64x2 w = *(const u64x2*)&sWg2[k * 16 + lq];
                fma2(gg0, a2, w.x); fma2(gg1, a2, w.y);
            }
        }
        const float di = __ldg(dist + e);
        const float co = (di < 10.0f) ? 0.5f * (__cosf(di * 0.31415926535f) + 1.0f) : 0.0f;
        float esu[4];
        { float x0, x1, x2, x3; up2(gg0, x0, x1); up2(gg1, x2, x3);
          esu[0] = sigmf(x0) * co; esu[1] = sigmf(x1) * co;
          esu[2] = sigmf(x2) * co; esu[3] = sigmf(x3) * co; }

        // edge scalar out + scatter (before tv, frees es regs)
        {
            float4 eso;
            eso.x = es[0] + esu[0]; eso.y = es[1] + esu[1];
            eso.z = es[2] + esu[2]; eso.w = es[3] + esu[3];
            *(float4*)(es_out + (size_t)e * LG + lq) = eso;
            red_v4(g_nes + (size_t)d * LG + lq, esu[0], esu[1], esu[2], esu[3]);
        }

        // vc = es_upd @ Wtv + btv -> tc | ec | rc
        u64 tc0, tc1, ec0, ec1, rc0, rc1;
        { u64x2 b0 = *(const u64x2*)&sbtv[lq];      tc0 = b0.x; tc1 = b0.y;
          u64x2 b1 = *(const u64x2*)&sbtv[16 + lq]; ec0 = b1.x; ec1 = b1.y;
          u64x2 b2 = *(const u64x2*)&sbtv[32 + lq]; rc0 = b2.x; rc1 = b2.y; }
#pragma unroll
        for (int kq = 0; kq < 4; kq++) {
#pragma unroll
            for (int c = 0; c < 4; c++) {
                const int k = kq * 4 + c;
                u64 a2 = dup2(__shfl_sync(0xffffffffu, esu[c], qb + kq));
                u64x2 wt = *(const u64x2*)&sWtv[k * 48 + lq];
                u64x2 we = *(const u64x2*)&sWtv[k * 48 + 16 + lq];
                u64x2 wr = *(const u64x2*)&sWtv[k * 48 + 32 + lq];
                fma2(tc0, a2, wt.x); fma2(tc1, a2, wt.y);
                fma2(ec0, a2, we.x); fma2(ec1, a2, we.y);
                fma2(rc0, a2, wr.x); fma2(rc1, a2, wr.y);
            }
        }

        // edge vector out + scatter
        const u64 co2 = dup2(co);
#pragma unroll
        for (int v = 0; v < 3; v++) {
            u64x2 ev  = *(const u64x2*)(edge_v + (size_t)e * 48 + v * 16 + lq);
            u64x2 nvv = *(const u64x2*)(g_nv + (size_t)s * 48 + v * 16 + lq);
            const u64 vn2 = dup2(__ldg(vctr + (size_t)e * 3 + v));
            u64 u0 = mul2(ev.x, tc0); fma2(u0, nvv.x, ec0); fma2(u0, vn2, rc0); u0 = mul2(u0, co2);
            u64 u1 = mul2(ev.y, tc1); fma2(u1, nvv.y, ec1); fma2(u1, vn2, rc1); u1 = mul2(u1, co2);
            u64x2 o; o.x = add2(ev.x, u0); o.y = add2(ev.y, u1);
            *(u64x2*)(ev_out + (size_t)e * 48 + v * 16 + lq) = o;
            float e0, e1, e2, e3; up2(u0, e0, e1); up2(u1, e2, e3);
            red_v4(g_nev + (size_t)d * 48 + v * 16 + lq, e0, e1, e2, e3);
        }
    }
}

// ============================================================================
// Kernel C: node output — warp per node, f32x2 main loop, grid-stride
// ============================================================================
__global__ void __launch_bounds__(256, 4) k_node_post(
    const float* __restrict__ node_s, const float* __restrict__ node_v,
    const float* __restrict__ Wonv,
    const float* __restrict__ Wo1,  const float* __restrict__ bo1,
    const float* __restrict__ Wo2,  const float* __restrict__ bo2,
    const float* __restrict__ ln_g, const float* __restrict__ ln_b,
    const float* __restrict__ cn_scale,
    float* __restrict__ s_out, float* __restrict__ v_out)
{
    __shared__ __align__(16) float sWonv[16 * 128];
    __shared__ __align__(16) float sWo2[16 * 128];
    __shared__ __align__(16) float sWo1[32 * 16];
    __shared__ float sbo1[16];
    const int t = threadIdx.x;
    for (int i = t; i < 2048; i += 256) { sWonv[i] = Wonv[i]; sWo2[i] = Wo2[i]; }
    for (int i = t; i < 512; i += 256) sWo1[i] = Wo1[i];
    if (t < 16) sbo1[t] = bo1[t];
    __syncthreads();

    const int lane = t & 31;

    for (int nb = blockIdx.x; nb < NN / 8; nb += gridDim.x) {   // NN = 6250*8, exact
        const int n = nb * 8 + (t >> 5);

        float nes = 0.f, nvn = 0.f, q0 = 0.f, q1 = 0.f, q2 = 0.f;
        if (lane < 16) {
            nes = g_nes[n * LG + lane];
            nvn = g_nvn[n * LG + lane];
            q0  = g_nev[(size_t)n * 48 + lane];
            q1  = g_nev[(size_t)n * 48 + 16 + lane];
            q2  = g_nev[(size_t)n * 48 + 32 + lane];
        }

        // h = silu([n_es | nv_norm] @ Wo1 + bo1)
        const int ll = lane & 15;
        float h = sbo1[ll];
#pragma unroll
        for (int k = 0; k < 16; k++) {
            h = fmaf(__shfl_sync(0xffffffffu, nes, k), sWo1[k * 16 + ll], h);
            h = fmaf(__shfl_sync(0xffffffffu, nvn, k), sWo1[(16 + k) * 16 + ll], h);
        }
        h = siluf(h);

        // lane owns g = lane*4 .. lane*4+3 (f32x2 pairs)
        u64 acc0, acc1;
        { float4 b2v = __ldg((const float4*)bo2 + lane);
          acc0 = pk2(b2v.x, b2v.y); acc1 = pk2(b2v.z, b2v.w); }
        u64 a00 = 0, a01 = 0, a10 = 0, a11 = 0, a20 = 0, a21 = 0;
#pragma unroll
        for (int j = 0; j < 16; j++) {
            u64 h2 = dup2(__shfl_sync(0xffffffffu, h, j));
            u64x2 w2 = *(const u64x2*)&sWo2[j * 128 + lane * 4];
            fma2(acc0, h2, w2.x); fma2(acc1, h2, w2.y);
            u64 b0 = dup2(__shfl_sync(0xffffffffu, q0, j));
            u64 b1 = dup2(__shfl_sync(0xffffffffu, q1, j));
            u64 b2 = dup2(__shfl_sync(0xffffffffu, q2, j));
            u64x2 wv = *(const u64x2*)&sWonv[j * 128 + lane * 4];
            fma2(a00, b0, wv.x); fma2(a01, b0, wv.y);
            fma2(a10, b1, wv.x); fma2(a11, b1, wv.y);
            fma2(a20, b2, wv.x); fma2(a21, b2, wv.y);
        }
        float4 acc, a0f, a1f, a2f;
        up2(acc0, acc.x, acc.y); up2(acc1, acc.z, acc.w);
        up2(a00, a0f.x, a0f.y);  up2(a01, a0f.z, a0f.w);
        up2(a10, a1f.x, a1f.y);  up2(a11, a1f.z, a1f.w);
        up2(a20, a2f.x, a2f.y);  up2(a21, a2f.z, a2f.w);

        // scalar residual + LayerNorm
        float4 s_in = __ldg((const float4*)(node_s + (size_t)n * GD) + lane);
        float4 so;
        so.x = s_in.x + acc.x; so.y = s_in.y + acc.y;
        so.z = s_in.z + acc.z; so.w = s_in.w + acc.w;
        float sum = so.x + so.y + so.z + so.w;
        float sq  = so.x * so.x + so.y * so.y + so.z * so.z + so.w * so.w;
#pragma unroll
        for (int off = 16; off > 0; off >>= 1) {
            sum += __shfl_xor_sync(0xffffffffu, sum, off);
            sq  += __shfl_xor_sync(0xffffffffu, sq, off);
        }
        float mu  = sum * (1.0f / 128.0f);
        float var = sq * (1.0f / 128.0f) - mu * mu;
        float inv = rsqrtf(var + 1e-5f);
        float4 g4 = __ldg((const float4*)ln_g + lane);
        float4 b4 = __ldg((const float4*)ln_b + lane);
        float4 os;
        os.x = (so.x - mu) * inv * g4.x + b4.x;
        os.y = (so.y - mu) * inv * g4.y + b4.y;
        os.z = (so.z - mu) * inv * g4.z + b4.z;
        os.w = (so.w - mu) * inv * g4.w + b4.w;
        ((float4*)(s_out + (size_t)n * GD))[lane] = os;

        // vector residual + CoorsNorm
        float4 v0 = __ldg((const float4*)(node_v + (size_t)n * 3 * GD) + lane);
        float4 v1 = __ldg((const float4*)(node_v + (size_t)n * 3 * GD + GD) + lane);
        float4 v2 = __ldg((const float4*)(node_v + (size_t)n * 3 * GD + 2 * GD) + lane);
        v0.x += a0f.x; v0.y += a0f.y; v0.z += a0f.z; v0.w += a0f.w;
        v1.x += a1f.x; v1.y += a1f.y; v1.z += a1f.z; v1.w += a1f.w;
        v2.x += a2f.x; v2.y += a2f.y; v2.z += a2f.z; v2.w += a2f.w;
        float4 c4 = __ldg((const float4*)cn_scale + lane);
        float nx = fmaxf(sqrtf(v0.x * v0.x + v1.x * v1.x + v2.x * v2.x), 1e-8f);
        float ny = fmaxf(sqrtf(v0.y * v0.y + v1.y * v1.y + v2.y * v2.y), 1e-8f);
        float nz = fmaxf(sqrtf(v0.z * v0.z + v1.z * v1.z + v2.z * v2.z), 1e-8f);
        float nw = fmaxf(sqrtf(v0.w * v0.w + v1.w * v1.w + v2.w * v2.w), 1e-8f);
        float sx = c4.x / nx, sy = c4.y / ny, sz = c4.z / nz, sw = c4.w / nw;
        v0.x *= sx; v0.y *= sy; v0.z *= sz; v0.w *= sw;
        v1.x *= sx; v1.y *= sy; v1.z *= sz; v1.w *= sw;
        v2.x *= sx; v2.y *= sy; v2.z *= sz; v2.w *= sw;
        ((float4*)(v_out + (size_t)n * 3 * GD))[lane]          = v0;
        ((float4*)(v_out + (size_t)n * 3 * GD + GD))[lane]     = v1;
        ((float4*)(v_out + (size_t)n * 3 * GD + 2 * GD))[lane] = v2;
    }
}

// ============================================================================
extern "C" void kernel_launch(void* const* d_in, const int* in_sizes, int n_in,
                              void* d_out, int out_size)
{
    const float* node_s = (const float*)d_in[0];
    const float* node_v = (const float*)d_in[1];
    const float* edge_s = (const float*)d_in[2];
    const float* edge_v = (const float*)d_in[3];
    const float* dist   = (const float*)d_in[4];
    const float* vctr   = (const float*)d_in[5];
    const int*   src    = (const int*)d_in[6];
    const int*   dst    = (const int*)d_in[7];
    const float* Wns  = (const float*)d_in[8];
    const float* bns  = (const float*)d_in[9];
    const float* Wnv  = (const float*)d_in[10];
    const float* Wen  = (const float*)d_in[11];
    const float* ben  = (const float*)d_in[12];
    const float* Wtp  = (const float*)d_in[13];
    const float* btp  = (const float*)d_in[14];
    const float* Wg1  = (const float*)d_in[15];
    const float* bg1  = (const float*)d_in[16];
    const float* Wg2  = (const float*)d_in[17];
    const float* bg2  = (const float*)d_in[18];
    const float* Wtv  = (const float*)d_in[19];
    const float* btv  = (const float*)d_in[20];
    const float* Wonv = (const float*)d_in[21];
    const float* Wo1  = (const float*)d_in[22];
    const float* bo1  = (const float*)d_in[23];
    const float* Wo2  = (const float*)d_in[24];
    const float* bo2  = (const float*)d_in[25];
    const float* ln_g = (const float*)d_in[26];
    const float* ln_b = (const float*)d_in[27];
    const float* cn_s = (const float*)d_in[28];

    float* out    = (float*)d_out;
    float* s_out  = out;                                 // [N, G]
    float* v_out  = out + (size_t)NN * GD;               // [N, 3, G]
    float* es_out = out + (size_t)NN * GD * 4;           // [E, LG]
    float* ev_out = es_out + (size_t)NE * LG;            // [E, 3, LG]

    const int PBLK = 592;   // 4 per SM, persistent grid-stride

    k_node_pre<<<PBLK, 256>>>(node_s, node_v, Wns, bns, Wnv);
    k_edge<<<PBLK, 256>>>(edge_s, edge_v, dist, vctr, src, dst,
                          Wen, ben, Wtp, btp, Wg1, bg1, Wg2, bg2, Wtv, btv,
                          es_out, ev_out);
    k_node_post<<<PBLK, 256>>>(node_s, node_v, Wonv, Wo1, bo1, Wo2, bo2,
                               ln_g, ln_b, cn_s, s_out, v_out);
}

// round 13
// speedup vs baseline: 1.1290x; 1.1290x over previous
#include <cuda_runtime.h>
#include <math.h>

#define NN 50000
#define NE 800000
#define GD 128
#define LG 16

// ---- scratch (device globals: no allocations allowed) ----
__device__ float g_ns [NN * LG];        // silu(node_s @ Wns + bns)
__device__ float g_nv [NN * 3 * LG];    // node_v @ Wnv
__device__ float g_nvn[NN * LG];        // ||nv||_spatial
__device__ float g_nes[NN * LG];        // segment_sum(es_upd)
__device__ float g_nev[NN * 3 * LG];    // segment_sum(ev_upd)

// ---- edge weights in constant bank (uniform LDCU path, off the MIO pipe) ----
__constant__ __align__(16) float cWen[32 * 16];
__constant__ __align__(16) float cWtp[16 * 16];
__constant__ __align__(16) float cWg1[16 * 16];
__constant__ __align__(16) float cWg2[16 * 16];
__constant__ __align__(16) float cWtv[16 * 48];
__constant__ __align__(16) float cben[16];
__constant__ __align__(16) float cbtp[16];
__constant__ __align__(16) float cbg1[16];
__constant__ __align__(16) float cbg2[16];
__constant__ __align__(16) float cbtv[48];

typedef unsigned long long u64;

__device__ __forceinline__ float siluf(float x)  { return x / (1.0f + __expf(-x)); }
__device__ __forceinline__ float sigmf(float x)  { return 1.0f / (1.0f + __expf(-x)); }

__device__ __forceinline__ u64 dup2(float v) {
    u64 r; asm("mov.b64 %0, {%1, %1};" : "=l"(r) : "f"(v)); return r;
}
__device__ __forceinline__ u64 pk2(float lo, float hi) {
    u64 r; asm("mov.b64 %0, {%1, %2};" : "=l"(r) : "f"(lo), "f"(hi)); return r;
}
__device__ __forceinline__ void up2(u64 v, float& lo, float& hi) {
    asm("mov.b64 {%0, %1}, %2;" : "=f"(lo), "=f"(hi) : "l"(v));
}
__device__ __forceinline__ void fma2(u64& d, u64 a, u64 b) {
    asm("fma.rn.f32x2 %0, %1, %2, %0;" : "+l"(d) : "l"(a), "l"(b));
}
__device__ __forceinline__ u64 mul2(u64 a, u64 b) {
    u64 r; asm("mul.rn.f32x2 %0, %1, %2;" : "=l"(r) : "l"(a), "l"(b)); return r;
}
__device__ __forceinline__ u64 add2(u64 a, u64 b) {
    u64 r; asm("add.rn.f32x2 %0, %1, %2;" : "=l"(r) : "l"(a), "l"(b)); return r;
}
__device__ __forceinline__ void red_v4(float* p, float a, float b, float c, float d) {
    asm volatile("red.global.add.v4.f32 [%0], {%1, %2, %3, %4};"
                 :: "l"(p), "f"(a), "f"(b), "f"(c), "f"(d) : "memory");
}

// ============================================================================
// Kernel A: node input projections — quad per node (R8 version, measured best)
//           + zero accumulators
// ============================================================================
__global__ void __launch_bounds__(256) k_node_pre(
    const float* __restrict__ node_s, const float* __restrict__ node_v,
    const float* __restrict__ Wns,    const float* __restrict__ bns,
    const float* __restrict__ Wnv)
{
    __shared__ float sWns[GD * LG];   // [g][l] row-major, as stored
    __shared__ float sWnv[GD * LG];
    for (int i = threadIdx.x; i < GD * LG; i += blockDim.x) {
        sWns[i] = Wns[i];
        sWnv[i] = Wnv[i];
    }
    // zero the edge-aggregation accumulators (kernel boundary orders vs k_edge)
    {
        int idx = blockIdx.x * blockDim.x + threadIdx.x;
        int tot = gridDim.x * blockDim.x;
        float4 z = make_float4(0.f, 0.f, 0.f, 0.f);
        float4* pes = (float4*)g_nes;
        float4* pev = (float4*)g_nev;
        for (int i = idx; i < NN * LG / 4; i += tot)     pes[i] = z;
        for (int i = idx; i < NN * 3 * LG / 4; i += tot) pev[i] = z;
    }
    __syncthreads();

    const int t    = threadIdx.x;
    const int q    = t & 3;
    const int lq   = q * 4;
    const int lane = t & 31;
    const unsigned qb = (unsigned)(lane & 28);
    int n = blockIdx.x * 64 + (t >> 2);
    const bool valid = (n < NN);
    if (!valid) n = NN - 1;

    const float* srow = node_s + (size_t)n * GD;
    const float* vrow = node_v + (size_t)n * 3 * GD;

    float4 ans = make_float4(0.f, 0.f, 0.f, 0.f);
    float4 av0 = ans, av1 = ans, av2 = ans;

    for (int tile = 0; tile < 4; tile++) {       // 32 g per tile
        float sA[2][4], vA[3][2][4];
#pragma unroll
        for (int j = 0; j < 2; j++) {
            int off = tile * 32 + j * 16 + lq;
            float4 tp = __ldg((const float4*)(srow + off));
            sA[j][0] = tp.x; sA[j][1] = tp.y; sA[j][2] = tp.z; sA[j][3] = tp.w;
#pragma unroll
            for (int v = 0; v < 3; v++) {
                float4 tv = __ldg((const float4*)(vrow + v * GD + off));
                vA[v][j][0] = tv.x; vA[v][j][1] = tv.y; vA[v][j][2] = tv.z; vA[v][j][3] = tv.w;
            }
        }
#pragma unroll
        for (int j = 0; j < 2; j++) {
#pragma unroll
            for (int kq = 0; kq < 4; kq++) {
#pragma unroll
                for (int c = 0; c < 4; c++) {
                    int gl = tile * 32 + j * 16 + kq * 4 + c;
                    float a  = __shfl_sync(0xffffffffu, sA[j][c],    qb + kq);
                    float b0 = __shfl_sync(0xffffffffu, vA[0][j][c], qb + kq);
                    float b1 = __shfl_sync(0xffffffffu, vA[1][j][c], qb + kq);
                    float b2 = __shfl_sync(0xffffffffu, vA[2][j][c], qb + kq);
                    float4 w = *(const float4*)(&sWns[gl * 16 + lq]);
                    float4 u = *(const float4*)(&sWnv[gl * 16 + lq]);
                    ans.x = fmaf(a, w.x, ans.x); ans.y = fmaf(a, w.y, ans.y);
                    ans.z = fmaf(a, w.z, ans.z); ans.w = fmaf(a, w.w, ans.w);
                    av0.x = fmaf(b0, u.x, av0.x); av0.y = fmaf(b0, u.y, av0.y);
                    av0.z = fmaf(b0, u.z, av0.z); av0.w = fmaf(b0, u.w, av0.w);
                    av1.x = fmaf(b1, u.x, av1.x); av1.y = fmaf(b1, u.y, av1.y);
                    av1.z = fmaf(b1, u.z, av1.z); av1.w = fmaf(b1, u.w, av1.w);
                    av2.x = fmaf(b2, u.x, av2.x); av2.y = fmaf(b2, u.y, av2.y);
                    av2.z = fmaf(b2, u.z, av2.z); av2.w = fmaf(b2, u.w, av2.w);
                }
            }
        }
    }

    if (valid) {
        float4 bb = __ldg((const float4*)(bns + lq));
        float4 o;
        o.x = siluf(ans.x + bb.x); o.y = siluf(ans.y + bb.y);
        o.z = siluf(ans.z + bb.z); o.w = siluf(ans.w + bb.w);
        *(float4*)(g_ns + (size_t)n * LG + lq) = o;
        *(float4*)(g_nv + (size_t)n * 48 + lq)      = av0;
        *(float4*)(g_nv + (size_t)n * 48 + 16 + lq) = av1;
        *(float4*)(g_nv + (size_t)n * 48 + 32 + lq) = av2;
        float4 nn;
        nn.x = sqrtf(av0.x * av0.x + av1.x * av1.x + av2.x * av2.x + 1e-12f);
        nn.y = sqrtf(av0.y * av0.y + av1.y * av1.y + av2.y * av2.y + 1e-12f);
        nn.z = sqrtf(av0.z * av0.z + av1.z * av1.z + av2.z * av2.z + 1e-12f);
        nn.w = sqrtf(av0.w * av0.w + av1.w * av1.w + av2.w * av2.w + 1e-12f);
        *(float4*)(g_nvn + (size_t)n * LG + lq) = nn;
    }
}

// ============================================================================
// Kernel B: edge update — THREAD per edge, weights from __constant__ (LDCU),
//           zero shuffles, zero shared memory, f32x2 math, vector atomics
// ============================================================================
__global__ void __launch_bounds__(128) k_edge(
    const float* __restrict__ edge_s, const float* __restrict__ edge_v,
    const float* __restrict__ dist,   const float* __restrict__ vctr,
    const int*   __restrict__ src,    const int*   __restrict__ dst,
    float* __restrict__ es_out,       float* __restrict__ ev_out)
{
    const int e = blockIdx.x * 128 + threadIdx.x;    // NE = 6250*128, exact
    const int s = src[e], d = dst[e];

    // gather inputs (coalesced / L2-resident)
    float nss[16], nsd[16], es[16];
#pragma unroll
    for (int i = 0; i < 4; i++) {
        float4 a = *(const float4*)(g_ns + (size_t)s * LG + 4 * i);
        nss[4*i] = a.x; nss[4*i+1] = a.y; nss[4*i+2] = a.z; nss[4*i+3] = a.w;
        float4 b = *(const float4*)(g_ns + (size_t)d * LG + 4 * i);
        nsd[4*i] = b.x; nsd[4*i+1] = b.y; nsd[4*i+2] = b.z; nsd[4*i+3] = b.w;
        float4 c = __ldg((const float4*)(edge_s + (size_t)e * LG) + i);
        es[4*i]  = c.x; es[4*i+1]  = c.y; es[4*i+2]  = c.z; es[4*i+3]  = c.w;
    }

    const u64* wEn = (const u64*)cWen;
    const u64* wTp = (const u64*)cWtp;
    const u64* wG1 = (const u64*)cWg1;
    const u64* wG2 = (const u64*)cWg2;
    const u64* wTv = (const u64*)cWtv;

    // en = [ns[src] | ns[dst]] @ Wen + ben
    u64 en[8];
#pragma unroll
    for (int j = 0; j < 8; j++) en[j] = ((const u64*)cben)[j];
#pragma unroll
    for (int k = 0; k < 16; k++) {
        u64 a = dup2(nss[k]);
#pragma unroll
        for (int j = 0; j < 8; j++) fma2(en[j], a, wEn[k * 8 + j]);
    }
#pragma unroll
    for (int k = 0; k < 16; k++) {
        u64 a = dup2(nsd[k]);
#pragma unroll
        for (int j = 0; j < 8; j++) fma2(en[j], a, wEn[128 + k * 8 + j]);
    }

    // tp = edge_s @ Wtp + btp ; tm = en * tp
    u64 tp[8];
#pragma unroll
    for (int j = 0; j < 8; j++) tp[j] = ((const u64*)cbtp)[j];
#pragma unroll
    for (int k = 0; k < 16; k++) {
        u64 a = dup2(es[k]);
#pragma unroll
        for (int j = 0; j < 8; j++) fma2(tp[j], a, wTp[k * 8 + j]);
    }
    float tm[16];
#pragma unroll
    for (int j = 0; j < 8; j++) {
        u64 m = mul2(en[j], tp[j]);
        up2(m, tm[2*j], tm[2*j+1]);
    }

    // h = silu(tm @ Wg1 + bg1)
    u64 h[8];
#pragma unroll
    for (int j = 0; j < 8; j++) h[j] = ((const u64*)cbg1)[j];
#pragma unroll
    for (int k = 0; k < 16; k++) {
        u64 a = dup2(tm[k]);
#pragma unroll
        for (int j = 0; j < 8; j++) fma2(h[j], a, wG1[k * 8 + j]);
    }
    float hh[16];
#pragma unroll
    for (int j = 0; j < 8; j++) {
        float x0, x1; up2(h[j], x0, x1);
        hh[2*j] = siluf(x0); hh[2*j+1] = siluf(x1);
    }

    // gate = sigmoid(h @ Wg2 + bg2), esu = gate * co
    u64 g[8];
#pragma unroll
    for (int j = 0; j < 8; j++) g[j] = ((const u64*)cbg2)[j];
#pragma unroll
    for (int k = 0; k < 16; k++) {
        u64 a = dup2(hh[k]);
#pragma unroll
        for (int j = 0; j < 8; j++) fma2(g[j], a, wG2[k * 8 + j]);
    }
    const float di = __ldg(dist + e);
    const float co = (di < 10.0f) ? 0.5f * (__cosf(di * 0.31415926535f) + 1.0f) : 0.0f;
    float esu[16];
#pragma unroll
    for (int j = 0; j < 8; j++) {
        float x0, x1; up2(g[j], x0, x1);
        esu[2*j]   = sigmf(x0) * co;
        esu[2*j+1] = sigmf(x1) * co;
    }

    // edge scalar out + scatter
#pragma unroll
    for (int i = 0; i < 4; i++) {
        float4 o;
        o.x = es[4*i]   + esu[4*i];
        o.y = es[4*i+1] + esu[4*i+1];
        o.z = es[4*i+2] + esu[4*i+2];
        o.w = es[4*i+3] + esu[4*i+3];
        *((float4*)(es_out + (size_t)e * LG) + i) = o;
        red_v4(g_nes + (size_t)d * LG + 4 * i,
               esu[4*i], esu[4*i+1], esu[4*i+2], esu[4*i+3]);
    }

    // vc = es_upd @ Wtv + btv -> tc | ec | rc
    u64 tc[8], ec[8], rc[8];
#pragma unroll
    for (int j = 0; j < 8; j++) {
        tc[j] = ((const u64*)cbtv)[j];
        ec[j] = ((const u64*)cbtv)[8 + j];
        rc[j] = ((const u64*)cbtv)[16 + j];
    }
#pragma unroll
    for (int k = 0; k < 16; k++) {
        u64 a = dup2(esu[k]);
#pragma unroll
        for (int j = 0; j < 8; j++) {
            fma2(tc[j], a, wTv[k * 24 + j]);
            fma2(ec[j], a, wTv[k * 24 + 8 + j]);
            fma2(rc[j], a, wTv[k * 24 + 16 + j]);
        }
    }

    // edge vector out + scatter
    const u64 co2 = dup2(co);
#pragma unroll
    for (int v = 0; v < 3; v++) {
        const u64 vn2 = dup2(__ldg(vctr + (size_t)e * 3 + v));
#pragma unroll
        for (int i = 0; i < 4; i++) {
            float4 ev4 = __ldg((const float4*)(edge_v + (size_t)e * 48 + v * 16) + i);
            float4 nv4 = *(const float4*)(g_nv + (size_t)s * 48 + v * 16 + 4 * i);
            u64 e0 = pk2(ev4.x, ev4.y), e1 = pk2(ev4.z, ev4.w);
            u64 n0 = pk2(nv4.x, nv4.y), n1 = pk2(nv4.z, nv4.w);
            u64 u0 = mul2(e0, tc[2*i]);
            fma2(u0, n0, ec[2*i]);  fma2(u0, vn2, rc[2*i]);  u0 = mul2(u0, co2);
            u64 u1 = mul2(e1, tc[2*i+1]);
            fma2(u1, n1, ec[2*i+1]); fma2(u1, vn2, rc[2*i+1]); u1 = mul2(u1, co2);
            u64 o0 = add2(e0, u0), o1 = add2(e1, u1);
            float4 o; up2(o0, o.x, o.y); up2(o1, o.z, o.w);
            *((float4*)(ev_out + (size_t)e * 48 + v * 16) + i) = o;
            float f0, f1, f2, f3; up2(u0, f0, f1); up2(u1, f2, f3);
            red_v4(g_nev + (size_t)d * 48 + v * 16 + 4 * i, f0, f1, f2, f3);
        }
    }
}

// ============================================================================
// Kernel C: node output — warp per node (R8 version, measured good)
// ============================================================================
__global__ void __launch_bounds__(256) k_node_post(
    const float* __restrict__ node_s, const float* __restrict__ node_v,
    const float* __restrict__ Wonv,
    const float* __restrict__ Wo1,  const float* __restrict__ bo1,
    const float* __restrict__ Wo2,  const float* __restrict__ bo2,
    const float* __restrict__ ln_g, const float* __restrict__ ln_b,
    const float* __restrict__ cn_scale,
    float* __restrict__ s_out, float* __restrict__ v_out)
{
    __shared__ float sWonv[16 * 128];
    __shared__ float sWo2[16 * 128];
    __shared__ float sWo1[32 * 16];
    __shared__ float sbo1[16];
    int t = threadIdx.x;
    for (int i = t; i < 2048; i += 256) { sWonv[i] = Wonv[i]; sWo2[i] = Wo2[i]; }
    for (int i = t; i < 512; i += 256) sWo1[i] = Wo1[i];
    if (t < 16) sbo1[t] = bo1[t];
    __syncthreads();

    int lane = t & 31;
    int n = blockIdx.x * (blockDim.x >> 5) + (t >> 5);
    if (n >= NN) return;

    float nes = 0.f, nvn = 0.f, q0 = 0.f, q1 = 0.f, q2 = 0.f;
    if (lane < 16) {
        nes = g_nes[n * LG + lane];
        nvn = g_nvn[n * LG + lane];
        q0  = g_nev[(size_t)n * 48 + lane];
        q1  = g_nev[(size_t)n * 48 + 16 + lane];
        q2  = g_nev[(size_t)n * 48 + 32 + lane];
    }

    // h = silu([n_es | nv_norm] @ Wo1 + bo1)
    int ll = lane & 15;
    float h = sbo1[ll];
#pragma unroll
    for (int k = 0; k < 16; k++) {
        h = fmaf(__shfl_sync(0xffffffffu, nes, k), sWo1[k * 16 + ll], h);
        h = fmaf(__shfl_sync(0xffffffffu, nvn, k), sWo1[(16 + k) * 16 + ll], h);
    }
    h = siluf(h);

    // lane owns g = lane*4 .. lane*4+3
    float4 acc = __ldg((const float4*)bo2 + lane);
    float4 a0 = make_float4(0.f, 0.f, 0.f, 0.f), a1 = a0, a2 = a0;
#pragma unroll
    for (int j = 0; j < 16; j++) {
        float hj = __shfl_sync(0xffffffffu, h, j);
        float4 w2 = *(const float4*)(&sWo2[j * 128 + lane * 4]);
        acc.x = fmaf(hj, w2.x, acc.x); acc.y = fmaf(hj, w2.y, acc.y);
        acc.z = fmaf(hj, w2.z, acc.z); acc.w = fmaf(hj, w2.w, acc.w);
        float b0 = __shfl_sync(0xffffffffu, q0, j);
        float b1 = __shfl_sync(0xffffffffu, q1, j);
        float b2 = __shfl_sync(0xffffffffu, q2, j);
        float4 wv = *(const float4*)(&sWonv[j * 128 + lane * 4]);
        a0.x = fmaf(b0, wv.x, a0.x); a0.y = fmaf(b0, wv.y, a0.y);
        a0.z = fmaf(b0, wv.z, a0.z); a0.w = fmaf(b0, wv.w, a0.w);
        a1.x = fmaf(b1, wv.x, a1.x); a1.y = fmaf(b1, wv.y, a1.y);
        a1.z = fmaf(b1, wv.z, a1.z); a1.w = fmaf(b1, wv.w, a1.w);
        a2.x = fmaf(b2, wv.x, a2.x); a2.y = fmaf(b2, wv.y, a2.y);
        a2.z = fmaf(b2, wv.z, a2.z); a2.w = fmaf(b2, wv.w, a2.w);
    }

    // scalar residual + LayerNorm
    float4 s_in = __ldg((const float4*)(node_s + (size_t)n * GD) + lane);
    float4 so;
    so.x = s_in.x + acc.x; so.y = s_in.y + acc.y;
    so.z = s_in.z + acc.z; so.w = s_in.w + acc.w;
    float sum = so.x + so.y + so.z + so.w;
    float sq  = so.x * so.x + so.y * so.y + so.z * so.z + so.w * so.w;
#pragma unroll
    for (int off = 16; off > 0; off >>= 1) {
        sum += __shfl_xor_sync(0xffffffffu, sum, off);
        sq  += __shfl_xor_sync(0xffffffffu, sq, off);
    }
    float mu  = sum * (1.0f / 128.0f);
    float var = sq * (1.0f / 128.0f) - mu * mu;
    float inv = rsqrtf(var + 1e-5f);
    float4 g4 = __ldg((const float4*)ln_g + lane);
    float4 b4 = __ldg((const float4*)ln_b + lane);
    float4 os;
    os.x = (so.x - mu) * inv * g4.x + b4.x;
    os.y = (so.y - mu) * inv * g4.y + b4.y;
    os.z = (so.z - mu) * inv * g4.z + b4.z;
    os.w = (so.w - mu) * inv * g4.w + b4.w;
    ((float4*)(s_out + (size_t)n * GD))[lane] = os;

    // vector residual + CoorsNorm
    float4 v0 = __ldg((const float4*)(node_v + (size_t)n * 3 * GD) + lane);
    float4 v1 = __ldg((const float4*)(node_v + (size_t)n * 3 * GD + GD) + lane);
    float4 v2 = __ldg((const float4*)(node_v + (size_t)n * 3 * GD + 2 * GD) + lane);
    v0.x += a0.x; v0.y += a0.y; v0.z += a0.z; v0.w += a0.w;
    v1.x += a1.x; v1.y += a1.y; v1.z += a1.z; v1.w += a1.w;
    v2.x += a2.x; v2.y += a2.y; v2.z += a2.z; v2.w += a2.w;
    float4 c4 = __ldg((const float4*)cn_scale + lane);
    float nx = fmaxf(sqrtf(v0.x * v0.x + v1.x * v1.x + v2.x * v2.x), 1e-8f);
    float ny = fmaxf(sqrtf(v0.y * v0.y + v1.y * v1.y + v2.y * v2.y), 1e-8f);
    float nz = fmaxf(sqrtf(v0.z * v0.z + v1.z * v1.z + v2.z * v2.z), 1e-8f);
    float nw = fmaxf(sqrtf(v0.w * v0.w + v1.w * v1.w + v2.w * v2.w), 1e-8f);
    float sx = c4.x / nx, sy = c4.y / ny, sz = c4.z / nz, sw = c4.w / nw;
    v0.x *= sx; v0.y *= sy; v0.z *= sz; v0.w *= sw;
    v1.x *= sx; v1.y *= sy; v1.z *= sz; v1.w *= sw;
    v2.x *= sx; v2.y *= sy; v2.z *= sz; v2.w *= sw;
    ((float4*)(v_out + (size_t)n * 3 * GD))[lane]          = v0;
    ((float4*)(v_out + (size_t)n * 3 * GD + GD))[lane]     = v1;
    ((float4*)(v_out + (size_t)n * 3 * GD + 2 * GD))[lane] = v2;
}

// ============================================================================
extern "C" void kernel_launch(void* const* d_in, const int* in_sizes, int n_in,
                              void* d_out, int out_size)
{
    const float* node_s = (const float*)d_in[0];
    const float* node_v = (const float*)d_in[1];
    const float* edge_s = (const float*)d_in[2];
    const float* edge_v = (const float*)d_in[3];
    const float* dist   = (const float*)d_in[4];
    const float* vctr   = (const float*)d_in[5];
    const int*   src    = (const int*)d_in[6];
    const int*   dst    = (const int*)d_in[7];
    const float* Wns  = (const float*)d_in[8];
    const float* bns  = (const float*)d_in[9];
    const float* Wnv  = (const float*)d_in[10];
    const float* Wen  = (const float*)d_in[11];
    const float* ben  = (const float*)d_in[12];
    const float* Wtp  = (const float*)d_in[13];
    const float* btp  = (const float*)d_in[14];
    const float* Wg1  = (const float*)d_in[15];
    const float* bg1  = (const float*)d_in[16];
    const float* Wg2  = (const float*)d_in[17];
    const float* bg2  = (const float*)d_in[18];
    const float* Wtv  = (const float*)d_in[19];
    const float* btv  = (const float*)d_in[20];
    const float* Wonv = (const float*)d_in[21];
    const float* Wo1  = (const float*)d_in[22];
    const float* bo1  = (const float*)d_in[23];
    const float* Wo2  = (const float*)d_in[24];
    const float* bo2  = (const float*)d_in[25];
    const float* ln_g = (const float*)d_in[26];
    const float* ln_b = (const float*)d_in[27];
    const float* cn_s = (const float*)d_in[28];

    float* out    = (float*)d_out;
    float* s_out  = out;                                 // [N, G]
    float* v_out  = out + (size_t)NN * GD;               // [N, 3, G]
    float* es_out = out + (size_t)NN * GD * 4;           // [E, LG]
    float* ev_out = es_out + (size_t)NE * LG;            // [E, 3, LG]

    // stage edge weights into the constant bank (graph-capturable D2D memcpys)
    cudaMemcpyToSymbolAsync(cWen, Wen, 512 * sizeof(float), 0, cudaMemcpyDeviceToDevice, 0);
    cudaMemcpyToSymbolAsync(cWtp, Wtp, 256 * sizeof(float), 0, cudaMemcpyDeviceToDevice, 0);
    cudaMemcpyToSymbolAsync(cWg1, Wg1, 256 * sizeof(float), 0, cudaMemcpyDeviceToDevice, 0);
    cudaMemcpyToSymbolAsync(cWg2, Wg2, 256 * sizeof(float), 0, cudaMemcpyDeviceToDevice, 0);
    cudaMemcpyToSymbolAsync(cWtv, Wtv, 768 * sizeof(float), 0, cudaMemcpyDeviceToDevice, 0);
    cudaMemcpyToSymbolAsync(cben, ben, 16 * sizeof(float), 0, cudaMemcpyDeviceToDevice, 0);
    cudaMemcpyToSymbolAsync(cbtp, btp, 16 * sizeof(float), 0, cudaMemcpyDeviceToDevice, 0);
    cudaMemcpyToSymbolAsync(cbg1, bg1, 16 * sizeof(float), 0, cudaMemcpyDeviceToDevice, 0);
    cudaMemcpyToSymbolAsync(cbg2, bg2, 16 * sizeof(float), 0, cudaMemcpyDeviceToDevice, 0);
    cudaMemcpyToSymbolAsync(cbtv, btv, 48 * sizeof(float), 0, cudaMemcpyDeviceToDevice, 0);

    int blocksPre  = (NN + 63) / 64;       // quad per node, 64 nodes/block
    int blocksEdge = NE / 128;             // thread per edge, 128 edges/block (exact)
    int blocksPost = (NN * 32 + 255) / 256;

    k_node_pre<<<blocksPre, 256>>>(node_s, node_v, Wns, bns, Wnv);
    k_edge<<<blocksEdge, 128>>>(edge_s, edge_v, dist, vctr, src, dst,
                                es_out, ev_out);
    k_node_post<<<blocksPost, 256>>>(node_s, node_v, Wonv, Wo1, bo1, Wo2, bo2,
                                     ln_g, ln_b, cn_s, s_out, v_out);
}

// round 14
// speedup vs baseline: 1.1356x; 1.0058x over previous
#include <cuda_runtime.h>
#include <math.h>

#define NN 50000
#define NE 800000
#define GD 128
#define LG 16

// ---- scratch (device globals: no allocations allowed) ----
__device__ float g_ns [NN * LG];        // silu(node_s @ Wns + bns)
__device__ float g_nv [NN * 3 * LG];    // node_v @ Wnv
__device__ float g_nvn[NN * LG];        // ||nv||_spatial
__device__ float g_nes[NN * LG];        // segment_sum(es_upd)
__device__ float g_nev[NN * 3 * LG];    // segment_sum(ev_upd)

// ---- edge weights in constant bank (uniform LDCU path, off the MIO pipe) ----
__constant__ __align__(16) float cWen[32 * 16];
__constant__ __align__(16) float cWtp[16 * 16];
__constant__ __align__(16) float cWg1[16 * 16];
__constant__ __align__(16) float cWg2[16 * 16];
__constant__ __align__(16) float cWtv[16 * 48];
__constant__ __align__(16) float cben[16];
__constant__ __align__(16) float cbtp[16];
__constant__ __align__(16) float cbg1[16];
__constant__ __align__(16) float cbg2[16];
__constant__ __align__(16) float cbtv[48];

typedef unsigned long long u64;

__device__ __forceinline__ float siluf(float x)  { return x / (1.0f + __expf(-x)); }
__device__ __forceinline__ float sigmf(float x)  { return 1.0f / (1.0f + __expf(-x)); }

__device__ __forceinline__ u64 dup2(float v) {
    u64 r; asm("mov.b64 %0, {%1, %1};" : "=l"(r) : "f"(v)); return r;
}
__device__ __forceinline__ u64 pk2(float lo, float hi) {
    u64 r; asm("mov.b64 %0, {%1, %2};" : "=l"(r) : "f"(lo), "f"(hi)); return r;
}
__device__ __forceinline__ void up2(u64 v, float& lo, float& hi) {
    asm("mov.b64 {%0, %1}, %2;" : "=f"(lo), "=f"(hi) : "l"(v));
}
__device__ __forceinline__ void fma2(u64& d, u64 a, u64 b) {
    asm("fma.rn.f32x2 %0, %1, %2, %0;" : "+l"(d) : "l"(a), "l"(b));
}
__device__ __forceinline__ u64 mul2(u64 a, u64 b) {
    u64 r; asm("mul.rn.f32x2 %0, %1, %2;" : "=l"(r) : "l"(a), "l"(b)); return r;
}
__device__ __forceinline__ u64 add2(u64 a, u64 b) {
    u64 r; asm("add.rn.f32x2 %0, %1, %2;" : "=l"(r) : "l"(a), "l"(b)); return r;
}
__device__ __forceinline__ void red_v4(float* p, float a, float b, float c, float d) {
    asm volatile("red.global.add.v4.f32 [%0], {%1, %2, %3, %4};"
                 :: "l"(p), "f"(a), "f"(b), "f"(c), "f"(d) : "memory");
}

// ============================================================================
// Kernel A: node input projections — quad per node (R8 version, measured best)
//           + zero accumulators
// ============================================================================
__global__ void __launch_bounds__(256) k_node_pre(
    const float* __restrict__ node_s, const float* __restrict__ node_v,
    const float* __restrict__ Wns,    const float* __restrict__ bns,
    const float* __restrict__ Wnv)
{
    __shared__ float sWns[GD * LG];   // [g][l] row-major, as stored
    __shared__ float sWnv[GD * LG];
    for (int i = threadIdx.x; i < GD * LG; i += blockDim.x) {
        sWns[i] = Wns[i];
        sWnv[i] = Wnv[i];
    }
    // zero the edge-aggregation accumulators (kernel boundary orders vs k_edge)
    {
        int idx = blockIdx.x * blockDim.x + threadIdx.x;
        int tot = gridDim.x * blockDim.x;
        float4 z = make_float4(0.f, 0.f, 0.f, 0.f);
        float4* pes = (float4*)g_nes;
        float4* pev = (float4*)g_nev;
        for (int i = idx; i < NN * LG / 4; i += tot)     pes[i] = z;
        for (int i = idx; i < NN * 3 * LG / 4; i += tot) pev[i] = z;
    }
    __syncthreads();

    const int t    = threadIdx.x;
    const int q    = t & 3;
    const int lq   = q * 4;
    const int lane = t & 31;
    const unsigned qb = (unsigned)(lane & 28);
    int n = blockIdx.x * 64 + (t >> 2);
    const bool valid = (n < NN);
    if (!valid) n = NN - 1;

    const float* srow = node_s + (size_t)n * GD;
    const float* vrow = node_v + (size_t)n * 3 * GD;

    float4 ans = make_float4(0.f, 0.f, 0.f, 0.f);
    float4 av0 = ans, av1 = ans, av2 = ans;

    for (int tile = 0; tile < 4; tile++) {       // 32 g per tile
        float sA[2][4], vA[3][2][4];
#pragma unroll
        for (int j = 0; j < 2; j++) {
            int off = tile * 32 + j * 16 + lq;
            float4 tp = __ldg((const float4*)(srow + off));
            sA[j][0] = tp.x; sA[j][1] = tp.y; sA[j][2] = tp.z; sA[j][3] = tp.w;
#pragma unroll
            for (int v = 0; v < 3; v++) {
                float4 tv = __ldg((const float4*)(vrow + v * GD + off));
                vA[v][j][0] = tv.x; vA[v][j][1] = tv.y; vA[v][j][2] = tv.z; vA[v][j][3] = tv.w;
            }
        }
#pragma unroll
        for (int j = 0; j < 2; j++) {
#pragma unroll
            for (int kq = 0; kq < 4; kq++) {
#pragma unroll
                for (int c = 0; c < 4; c++) {
                    int gl = tile * 32 + j * 16 + kq * 4 + c;
                    float a  = __shfl_sync(0xffffffffu, sA[j][c],    qb + kq);
                    float b0 = __shfl_sync(0xffffffffu, vA[0][j][c], qb + kq);
                    float b1 = __shfl_sync(0xffffffffu, vA[1][j][c], qb + kq);
                    float b2 = __shfl_sync(0xffffffffu, vA[2][j][c], qb + kq);
                    float4 w = *(const float4*)(&sWns[gl * 16 + lq]);
                    float4 u = *(const float4*)(&sWnv[gl * 16 + lq]);
                    ans.x = fmaf(a, w.x, ans.x); ans.y = fmaf(a, w.y, ans.y);
                    ans.z = fmaf(a, w.z, ans.z); ans.w = fmaf(a, w.w, ans.w);
                    av0.x = fmaf(b0, u.x, av0.x); av0.y = fmaf(b0, u.y, av0.y);
                    av0.z = fmaf(b0, u.z, av0.z); av0.w = fmaf(b0, u.w, av0.w);
                    av1.x = fmaf(b1, u.x, av1.x); av1.y = fmaf(b1, u.y, av1.y);
                    av1.z = fmaf(b1, u.z, av1.z); av1.w = fmaf(b1, u.w, av1.w);
                    av2.x = fmaf(b2, u.x, av2.x); av2.y = fmaf(b2, u.y, av2.y);
                    av2.z = fmaf(b2, u.z, av2.z); av2.w = fmaf(b2, u.w, av2.w);
                }
            }
        }
    }

    if (valid) {
        float4 bb = __ldg((const float4*)(bns + lq));
        float4 o;
        o.x = siluf(ans.x + bb.x); o.y = siluf(ans.y + bb.y);
        o.z = siluf(ans.z + bb.z); o.w = siluf(ans.w + bb.w);
        *(float4*)(g_ns + (size_t)n * LG + lq) = o;
        *(float4*)(g_nv + (size_t)n * 48 + lq)      = av0;
        *(float4*)(g_nv + (size_t)n * 48 + 16 + lq) = av1;
        *(float4*)(g_nv + (size_t)n * 48 + 32 + lq) = av2;
        float4 nn;
        nn.x = sqrtf(av0.x * av0.x + av1.x * av1.x + av2.x * av2.x + 1e-12f);
        nn.y = sqrtf(av0.y * av0.y + av1.y * av1.y + av2.y * av2.y + 1e-12f);
        nn.z = sqrtf(av0.z * av0.z + av1.z * av1.z + av2.z * av2.z + 1e-12f);
        nn.w = sqrtf(av0.w * av0.w + av1.w * av1.w + av2.w * av2.w + 1e-12f);
        *(float4*)(g_nvn + (size_t)n * LG + lq) = nn;
    }
}

// ============================================================================
// Kernel B: edge update — THREAD per edge, weights from __constant__ (LDCU),
//           zero shuffles, zero shared memory, f32x2 math, vector atomics
// ============================================================================
__global__ void __launch_bounds__(128) k_edge(
    const float* __restrict__ edge_s, const float* __restrict__ edge_v,
    const float* __restrict__ dist,   const float* __restrict__ vctr,
    const int*   __restrict__ src,    const int*   __restrict__ dst,
    float* __restrict__ es_out,       float* __restrict__ ev_out)
{
    const int e = blockIdx.x * 128 + threadIdx.x;    // NE = 6250*128, exact
    const int s = src[e], d = dst[e];

    // gather inputs (coalesced / L2-resident)
    float nss[16], nsd[16], es[16];
#pragma unroll
    for (int i = 0; i < 4; i++) {
        float4 a = *(const float4*)(g_ns + (size_t)s * LG + 4 * i);
        nss[4*i] = a.x; nss[4*i+1] = a.y; nss[4*i+2] = a.z; nss[4*i+3] = a.w;
        float4 b = *(const float4*)(g_ns + (size_t)d * LG + 4 * i);
        nsd[4*i] = b.x; nsd[4*i+1] = b.y; nsd[4*i+2] = b.z; nsd[4*i+3] = b.w;
        float4 c = __ldg((const float4*)(edge_s + (size_t)e * LG) + i);
        es[4*i]  = c.x; es[4*i+1]  = c.y; es[4*i+2]  = c.z; es[4*i+3]  = c.w;
    }

    const u64* wEn = (const u64*)cWen;
    const u64* wTp = (const u64*)cWtp;
    const u64* wG1 = (const u64*)cWg1;
    const u64* wG2 = (const u64*)cWg2;
    const u64* wTv = (const u64*)cWtv;

    // en = [ns[src] | ns[dst]] @ Wen + ben
    u64 en[8];
#pragma unroll
    for (int j = 0; j < 8; j++) en[j] = ((const u64*)cben)[j];
#pragma unroll
    for (int k = 0; k < 16; k++) {
        u64 a = dup2(nss[k]);
#pragma unroll
        for (int j = 0; j < 8; j++) fma2(en[j], a, wEn[k * 8 + j]);
    }
#pragma unroll
    for (int k = 0; k < 16; k++) {
        u64 a = dup2(nsd[k]);
#pragma unroll
        for (int j = 0; j < 8; j++) fma2(en[j], a, wEn[128 + k * 8 + j]);
    }

    // tp = edge_s @ Wtp + btp ; tm = en * tp
    u64 tp[8];
#pragma unroll
    for (int j = 0; j < 8; j++) tp[j] = ((const u64*)cbtp)[j];
#pragma unroll
    for (int k = 0; k < 16; k++) {
        u64 a = dup2(es[k]);
#pragma unroll
        for (int j = 0; j < 8; j++) fma2(tp[j], a, wTp[k * 8 + j]);
    }
    float tm[16];
#pragma unroll
    for (int j = 0; j < 8; j++) {
        u64 m = mul2(en[j], tp[j]);
        up2(m, tm[2*j], tm[2*j+1]);
    }

    // h = silu(tm @ Wg1 + bg1)
    u64 h[8];
#pragma unroll
    for (int j = 0; j < 8; j++) h[j] = ((const u64*)cbg1)[j];
#pragma unroll
    for (int k = 0; k < 16; k++) {
        u64 a = dup2(tm[k]);
#pragma unroll
        for (int j = 0; j < 8; j++) fma2(h[j], a, wG1[k * 8 + j]);
    }
    float hh[16];
#pragma unroll
    for (int j = 0; j < 8; j++) {
        float x0, x1; up2(h[j], x0, x1);
        hh[2*j] = siluf(x0); hh[2*j+1] = siluf(x1);
    }

    // gate = sigmoid(h @ Wg2 + bg2), esu = gate * co
    u64 g[8];
#pragma unroll
    for (int j = 0; j < 8; j++) g[j] = ((const u64*)cbg2)[j];
#pragma unroll
    for (int k = 0; k < 16; k++) {
        u64 a = dup2(hh[k]);
#pragma unroll
        for (int j = 0; j < 8; j++) fma2(g[j], a, wG2[k * 8 + j]);
    }
    const float di = __ldg(dist + e);
    const float co = (di < 10.0f) ? 0.5f * (__cosf(di * 0.31415926535f) + 1.0f) : 0.0f;
    float esu[16];
#pragma unroll
    for (int j = 0; j < 8; j++) {
        float x0, x1; up2(g[j], x0, x1);
        esu[2*j]   = sigmf(x0) * co;
        esu[2*j+1] = sigmf(x1) * co;
    }

    // edge scalar out + scatter
#pragma unroll
    for (int i = 0; i < 4; i++) {
        float4 o;
        o.x = es[4*i]   + esu[4*i];
        o.y = es[4*i+1] + esu[4*i+1];
        o.z = es[4*i+2] + esu[4*i+2];
        o.w = es[4*i+3] + esu[4*i+3];
        *((float4*)(es_out + (size_t)e * LG) + i) = o;
        red_v4(g_nes + (size_t)d * LG + 4 * i,
               esu[4*i], esu[4*i+1], esu[4*i+2], esu[4*i+3]);
    }

    // vc = es_upd @ Wtv + btv -> tc | ec | rc
    u64 tc[8], ec[8], rc[8];
#pragma unroll
    for (int j = 0; j < 8; j++) {
        tc[j] = ((const u64*)cbtv)[j];
        ec[j] = ((const u64*)cbtv)[8 + j];
        rc[j] = ((const u64*)cbtv)[16 + j];
    }
#pragma unroll
    for (int k = 0; k < 16; k++) {
        u64 a = dup2(esu[k]);
#pragma unroll
        for (int j = 0; j < 8; j++) {
            fma2(tc[j], a, wTv[k * 24 + j]);
            fma2(ec[j], a, wTv[k * 24 + 8 + j]);
            fma2(rc[j], a, wTv[k * 24 + 16 + j]);
        }
    }

    // edge vector out + scatter
    const u64 co2 = dup2(co);
#pragma unroll
    for (int v = 0; v < 3; v++) {
        const u64 vn2 = dup2(__ldg(vctr + (size_t)e * 3 + v));
#pragma unroll
        for (int i = 0; i < 4; i++) {
            float4 ev4 = __ldg((const float4*)(edge_v + (size_t)e * 48 + v * 16) + i);
            float4 nv4 = *(const float4*)(g_nv + (size_t)s * 48 + v * 16 + 4 * i);
            u64 e0 = pk2(ev4.x, ev4.y), e1 = pk2(ev4.z, ev4.w);
            u64 n0 = pk2(nv4.x, nv4.y), n1 = pk2(nv4.z, nv4.w);
            u64 u0 = mul2(e0, tc[2*i]);
            fma2(u0, n0, ec[2*i]);  fma2(u0, vn2, rc[2*i]);  u0 = mul2(u0, co2);
            u64 u1 = mul2(e1, tc[2*i+1]);
            fma2(u1, n1, ec[2*i+1]); fma2(u1, vn2, rc[2*i+1]); u1 = mul2(u1, co2);
            u64 o0 = add2(e0, u0), o1 = add2(e1, u1);
            float4 o; up2(o0, o.x, o.y); up2(o1, o.z, o.w);
            *((float4*)(ev_out + (size_t)e * 48 + v * 16) + i) = o;
            float f0, f1, f2, f3; up2(u0, f0, f1); up2(u1, f2, f3);
            red_v4(g_nev + (size_t)d * 48 + v * 16 + 4 * i, f0, f1, f2, f3);
        }
    }
}

// ============================================================================
// Kernel C: node output — warp per node (R8 version, measured good)
// ============================================================================
__global__ void __launch_bounds__(256) k_node_post(
    const float* __restrict__ node_s, const float* __restrict__ node_v,
    const float* __restrict__ Wonv,
    const float* __restrict__ Wo1,  const float* __restrict__ bo1,
    const float* __restrict__ Wo2,  const float* __restrict__ bo2,
    const float* __restrict__ ln_g, const float* __restrict__ ln_b,
    const float* __restrict__ cn_scale,
    float* __restrict__ s_out, float* __restrict__ v_out)
{
    __shared__ float sWonv[16 * 128];
    __shared__ float sWo2[16 * 128];
    __shared__ float sWo1[32 * 16];
    __shared__ float sbo1[16];
    int t = threadIdx.x;
    for (int i = t; i < 2048; i += 256) { sWonv[i] = Wonv[i]; sWo2[i] = Wo2[i]; }
    for (int i = t; i < 512; i += 256) sWo1[i] = Wo1[i];
    if (t < 16) sbo1[t] = bo1[t];
    __syncthreads();

    int lane = t & 31;
    int n = blockIdx.x * (blockDim.x >> 5) + (t >> 5);
    if (n >= NN) return;

    float nes = 0.f, nvn = 0.f, q0 = 0.f, q1 = 0.f, q2 = 0.f;
    if (lane < 16) {
        nes = g_nes[n * LG + lane];
        nvn = g_nvn[n * LG + lane];
        q0  = g_nev[(size_t)n * 48 + lane];
        q1  = g_nev[(size_t)n * 48 + 16 + lane];
        q2  = g_nev[(size_t)n * 48 + 32 + lane];
    }

    // h = silu([n_es | nv_norm] @ Wo1 + bo1)
    int ll = lane & 15;
    float h = sbo1[ll];
#pragma unroll
    for (int k = 0; k < 16; k++) {
        h = fmaf(__shfl_sync(0xffffffffu, nes, k), sWo1[k * 16 + ll], h);
        h = fmaf(__shfl_sync(0xffffffffu, nvn, k), sWo1[(16 + k) * 16 + ll], h);
    }
    h = siluf(h);

    // lane owns g = lane*4 .. lane*4+3
    float4 acc = __ldg((const float4*)bo2 + lane);
    float4 a0 = make_float4(0.f, 0.f, 0.f, 0.f), a1 = a0, a2 = a0;
#pragma unroll
    for (int j = 0; j < 16; j++) {
        float hj = __shfl_sync(0xffffffffu, h, j);
        float4 w2 = *(const float4*)(&sWo2[j * 128 + lane * 4]);
        acc.x = fmaf(hj, w2.x, acc.x); acc.y = fmaf(hj, w2.y, acc.y);
        acc.z = fmaf(hj, w2.z, acc.z); acc.w = fmaf(hj, w2.w, acc.w);
        float b0 = __shfl_sync(0xffffffffu, q0, j);
        float b1 = __shfl_sync(0xffffffffu, q1, j);
        float b2 = __shfl_sync(0xffffffffu, q2, j);
        float4 wv = *(const float4*)(&sWonv[j * 128 + lane * 4]);
        a0.x = fmaf(b0, wv.x, a0.x); a0.y = fmaf(b0, wv.y, a0.y);
        a0.z = fmaf(b0, wv.z, a0.z); a0.w = fmaf(b0, wv.w, a0.w);
        a1.x = fmaf(b1, wv.x, a1.x); a1.y = fmaf(b1, wv.y, a1.y);
        a1.z = fmaf(b1, wv.z, a1.z); a1.w = fmaf(b1, wv.w, a1.w);
        a2.x = fmaf(b2, wv.x, a2.x); a2.y = fmaf(b2, wv.y, a2.y);
        a2.z = fmaf(b2, wv.z, a2.z); a2.w = fmaf(b2, wv.w, a2.w);
    }

    // scalar residual + LayerNorm
    float4 s_in = __ldg((const float4*)(node_s + (size_t)n * GD) + lane);
    float4 so;
    so.x = s_in.x + acc.x; so.y = s_in.y + acc.y;
    so.z = s_in.z + acc.z; so.w = s_in.w + acc.w;
    float sum = so.x + so.y + so.z + so.w;
    float sq  = so.x * so.x + so.y * so.y + so.z * so.z + so.w * so.w;
#pragma unroll
    for (int off = 16; off > 0; off >>= 1) {
        sum += __shfl_xor_sync(0xffffffffu, sum, off);
        sq  += __shfl_xor_sync(0xffffffffu, sq, off);
    }
    float mu  = sum * (1.0f / 128.0f);
    float var = sq * (1.0f / 128.0f) - mu * mu;
    float inv = rsqrtf(var + 1e-5f);
    float4 g4 = __ldg((const float4*)ln_g + lane);
    float4 b4 = __ldg((const float4*)ln_b + lane);
    float4 os;
    os.x = (so.x - mu) * inv * g4.x + b4.x;
    os.y = (so.y - mu) * inv * g4.y + b4.y;
    os.z = (so.z - mu) * inv * g4.z + b4.z;
    os.w = (so.w - mu) * inv * g4.w + b4.w;
    ((float4*)(s_out + (size_t)n * GD))[lane] = os;

    // vector residual + CoorsNorm
    float4 v0 = __ldg((const float4*)(node_v + (size_t)n * 3 * GD) + lane);
    float4 v1 = __ldg((const float4*)(node_v + (size_t)n * 3 * GD + GD) + lane);
    float4 v2 = __ldg((const float4*)(node_v + (size_t)n * 3 * GD + 2 * GD) + lane);
    v0.x += a0.x; v0.y += a0.y; v0.z += a0.z; v0.w += a0.w;
    v1.x += a1.x; v1.y += a1.y; v1.z += a1.z; v1.w += a1.w;
    v2.x += a2.x; v2.y += a2.y; v2.z += a2.z; v2.w += a2.w;
    float4 c4 = __ldg((const float4*)cn_scale + lane);
    float nx = fmaxf(sqrtf(v0.x * v0.x + v1.x * v1.x + v2.x * v2.x), 1e-8f);
    float ny = fmaxf(sqrtf(v0.y * v0.y + v1.y * v1.y + v2.y * v2.y), 1e-8f);
    float nz = fmaxf(sqrtf(v0.z * v0.z + v1.z * v1.z + v2.z * v2.z), 1e-8f);
    float nw = fmaxf(sqrtf(v0.w * v0.w + v1.w * v1.w + v2.w * v2.w), 1e-8f);
    float sx = c4.x / nx, sy = c4.y / ny, sz = c4.z / nz, sw = c4.w / nw;
    v0.x *= sx; v0.y *= sy; v0.z *= sz; v0.w *= sw;
    v1.x *= sx; v1.y *= sy; v1.z *= sz; v1.w *= sw;
    v2.x *= sx; v2.y *= sy; v2.z *= sz; v2.w *= sw;
    ((float4*)(v_out + (size_t)n * 3 * GD))[lane]          = v0;
    ((float4*)(v_out + (size_t)n * 3 * GD + GD))[lane]     = v1;
    ((float4*)(v_out + (size_t)n * 3 * GD + 2 * GD))[lane] = v2;
}

// ============================================================================
extern "C" void kernel_launch(void* const* d_in, const int* in_sizes, int n_in,
                              void* d_out, int out_size)
{
    const float* node_s = (const float*)d_in[0];
    const float* node_v = (const float*)d_in[1];
    const float* edge_s = (const float*)d_in[2];
    const float* edge_v = (const float*)d_in[3];
    const float* dist   = (const float*)d_in[4];
    const float* vctr   = (const float*)d_in[5];
    const int*   src    = (const int*)d_in[6];
    const int*   dst    = (const int*)d_in[7];
    const float* Wns  = (const float*)d_in[8];
    const float* bns  = (const float*)d_in[9];
    const float* Wnv  = (const float*)d_in[10];
    const float* Wen  = (const float*)d_in[11];
    const float* ben  = (const float*)d_in[12];
    const float* Wtp  = (const float*)d_in[13];
    const float* btp  = (const float*)d_in[14];
    const float* Wg1  = (const float*)d_in[15];
    const float* bg1  = (const float*)d_in[16];
    const float* Wg2  = (const float*)d_in[17];
    const float* bg2  = (const float*)d_in[18];
    const float* Wtv  = (const float*)d_in[19];
    const float* btv  = (const float*)d_in[20];
    const float* Wonv = (const float*)d_in[21];
    const float* Wo1  = (const float*)d_in[22];
    const float* bo1  = (const float*)d_in[23];
    const float* Wo2  = (const float*)d_in[24];
    const float* bo2  = (const float*)d_in[25];
    const float* ln_g = (const float*)d_in[26];
    const float* ln_b = (const float*)d_in[27];
    const float* cn_s = (const float*)d_in[28];

    float* out    = (float*)d_out;
    float* s_out  = out;                                 // [N, G]
    float* v_out  = out + (size_t)NN * GD;               // [N, 3, G]
    float* es_out = out + (size_t)NN * GD * 4;           // [E, LG]
    float* ev_out = es_out + (size_t)NE * LG;            // [E, 3, LG]

    // stage edge weights into the constant bank (graph-capturable D2D memcpys)
    cudaMemcpyToSymbolAsync(cWen, Wen, 512 * sizeof(float), 0, cudaMemcpyDeviceToDevice, 0);
    cudaMemcpyToSymbolAsync(cWtp, Wtp, 256 * sizeof(float), 0, cudaMemcpyDeviceToDevice, 0);
    cudaMemcpyToSymbolAsync(cWg1, Wg1, 256 * sizeof(float), 0, cudaMemcpyDeviceToDevice, 0);
    cudaMemcpyToSymbolAsync(cWg2, Wg2, 256 * sizeof(float), 0, cudaMemcpyDeviceToDevice, 0);
    cudaMemcpyToSymbolAsync(cWtv, Wtv, 768 * sizeof(float), 0, cudaMemcpyDeviceToDevice, 0);
    cudaMemcpyToSymbolAsync(cben, ben, 16 * sizeof(float), 0, cudaMemcpyDeviceToDevice, 0);
    cudaMemcpyToSymbolAsync(cbtp, btp, 16 * sizeof(float), 0, cudaMemcpyDeviceToDevice, 0);
    cudaMemcpyToSymbolAsync(cbg1, bg1, 16 * sizeof(float), 0, cudaMemcpyDeviceToDevice, 0);
    cudaMemcpyToSymbolAsync(cbg2, bg2, 16 * sizeof(float), 0, cudaMemcpyDeviceToDevice, 0);
    cudaMemcpyToSymbolAsync(cbtv, btv, 48 * sizeof(float), 0, cudaMemcpyDeviceToDevice, 0);

    int blocksPre  = (NN + 63) / 64;       // quad per node, 64 nodes/block
    int blocksEdge = NE / 128;             // thread per edge, 128 edges/block (exact)
    int blocksPost = (NN * 32 + 255) / 256;

    k_node_pre<<<blocksPre, 256>>>(node_s, node_v, Wns, bns, Wnv);
    k_edge<<<blocksEdge, 128>>>(edge_s, edge_v, dist, vctr, src, dst,
                                es_out, ev_out);
    k_node_post<<<blocksPost, 256>>>(node_s, node_v, Wonv, Wo1, bo1, Wo2, bo2,
                                     ln_g, ln_b, cn_s, s_out, v_out);
}